// round 1
// baseline (speedup 1.0000x reference)
#include <cuda_runtime.h>
#include <cstdint>

typedef unsigned long long u64;

// ---------- f32x2 packed math (sm_103a) ----------
__device__ __forceinline__ u64 pk2(float lo, float hi) {
    u64 r;
    asm("mov.b64 %0, {%1, %2};" : "=l"(r) : "r"(__float_as_uint(lo)), "r"(__float_as_uint(hi)));
    return r;
}
__device__ __forceinline__ void upk2(u64 v, float& lo, float& hi) {
    unsigned a, b;
    asm("mov.b64 {%0, %1}, %2;" : "=r"(a), "=r"(b) : "l"(v));
    lo = __uint_as_float(a); hi = __uint_as_float(b);
}
__device__ __forceinline__ u64 fma2(u64 a, u64 b, u64 c) {
    u64 d;
    asm("fma.rn.f32x2 %0, %1, %2, %3;" : "=l"(d) : "l"(a), "l"(b), "l"(c));
    return d;
}
__device__ __forceinline__ u64 add2(u64 a, u64 b) {
    u64 d;
    asm("add.rn.f32x2 %0, %1, %2;" : "=l"(d) : "l"(a), "l"(b));
    return d;
}

// ---------- per-point precomputed first-layer projections ----------
// A1/B1: feat @ l0_fc1_w[0:40]/[40:80]  (A1 has b1 folded in)
// A0/B0: feat @ l0_fc0_w[0:40]/[40:80]  (A0 has b0 folded in)
__device__ float g_A0[1024 * 32];
__device__ float g_B0[1024 * 32];
__device__ float g_A1[1024 * 32];
__device__ float g_B1[1024 * 32];

__global__ void ppf_pre(const float* __restrict__ feat,
                        const float* __restrict__ w0, const float* __restrict__ b0,
                        const float* __restrict__ w1, const float* __restrict__ b1) {
    int t = blockIdx.x * blockDim.x + threadIdx.x;   // 32768 threads
    int i = t >> 5, c = t & 31;
    const float* f = feat + i * 40;
    float a0 = b0[c], bo0 = 0.f, a1 = b1[c], bo1 = 0.f;
#pragma unroll 8
    for (int k = 0; k < 40; k++) {
        float fv = f[k];
        a0  = fmaf(fv, w0[k * 32 + c],        a0);
        bo0 = fmaf(fv, w0[(k + 40) * 32 + c], bo0);
        a1  = fmaf(fv, w1[k * 32 + c],        a1);
        bo1 = fmaf(fv, w1[(k + 40) * 32 + c], bo1);
    }
    g_A0[i * 32 + c] = a0;
    g_B0[i * 32 + c] = bo0;
    g_A1[i * 32 + c] = a1;
    g_B1[i * 32 + c] = bo1;
}

// ---------- shared memory layout (units: floats) ----------
#define O_W0P   0          // [4][32]  l0_fc0_w rows 80..83
#define O_W1P   128        // [4][32]  l0_fc1_w rows 80..83
#define O_L0W2  256        // [32][32]
#define O_L0B2  1280       // [32]
#define O_L1W1  1312       // [32][32]
#define O_L1B1  2336       // [32]
#define O_L1W2  2368       // [32][32]
#define O_L1B2  3392       // [32]
#define O_L2W0  3424       // [32][16]
#define O_L2B0  3936       // [16]
#define O_L2W1  3952       // [32][16]
#define O_L2B1  4464       // [16]
#define O_L2W2  4480       // [16][16]
#define O_L2B2  4736       // [16]
#define O_FW    4752       // [16][66]
#define O_FB    5808       // [66]
#define O_OUT   5888       // 8 warps * 32 lanes * 66
#define SMEM_FLOATS (5888 + 8 * 32 * 66)
#define SMEM_BYTES  (SMEM_FLOATS * 4)

__global__ __launch_bounds__(256, 2)
void ppf_main(const float* __restrict__ pc, const float* __restrict__ nrm,
              const float* __restrict__ dist,
              const float* __restrict__ fc0w, const float* __restrict__ fc1w,
              const float* __restrict__ l0w2, const float* __restrict__ l0b2,
              const float* __restrict__ l1w1, const float* __restrict__ l1b1,
              const float* __restrict__ l1w2, const float* __restrict__ l1b2,
              const float* __restrict__ l2w0, const float* __restrict__ l2b0,
              const float* __restrict__ l2w1, const float* __restrict__ l2b1,
              const float* __restrict__ l2w2, const float* __restrict__ l2b2,
              const float* __restrict__ fw, const float* __restrict__ fb,
              float* __restrict__ out) {
    extern __shared__ float s[];
    const int tid = threadIdx.x;
    const int lane = tid & 31;
    const int warp = tid >> 5;

    // cooperative weight staging
    {
        for (int t = tid; t < 128; t += 256)  s[O_W0P + t] = fc0w[80 * 32 + t];
        for (int t = tid; t < 128; t += 256)  s[O_W1P + t] = fc1w[80 * 32 + t];
        for (int t = tid; t < 1024; t += 256) s[O_L0W2 + t] = l0w2[t];
        for (int t = tid; t < 32; t += 256)   s[O_L0B2 + t] = l0b2[t];
        for (int t = tid; t < 1024; t += 256) s[O_L1W1 + t] = l1w1[t];
        for (int t = tid; t < 32; t += 256)   s[O_L1B1 + t] = l1b1[t];
        for (int t = tid; t < 1024; t += 256) s[O_L1W2 + t] = l1w2[t];
        for (int t = tid; t < 32; t += 256)   s[O_L1B2 + t] = l1b2[t];
        for (int t = tid; t < 512; t += 256)  s[O_L2W0 + t] = l2w0[t];
        for (int t = tid; t < 16; t += 256)   s[O_L2B0 + t] = l2b0[t];
        for (int t = tid; t < 512; t += 256)  s[O_L2W1 + t] = l2w1[t];
        for (int t = tid; t < 16; t += 256)   s[O_L2B1 + t] = l2b1[t];
        for (int t = tid; t < 256; t += 256)  s[O_L2W2 + t] = l2w2[t];
        for (int t = tid; t < 16; t += 256)   s[O_L2B2 + t] = l2b2[t];
        for (int t = tid; t < 1056; t += 256) s[O_FW + t] = fw[t];
        for (int t = tid; t < 66; t += 256)   s[O_FB + t] = fb[t];
    }
    __syncthreads();

    const int i = blockIdx.x >> 2;
    const int j = ((blockIdx.x & 3) << 8) | tid;

    // ---- PPF features ----
    float pcix = pc[3 * i], pciy = pc[3 * i + 1], pciz = pc[3 * i + 2];
    float pcjx = pc[3 * j], pcjy = pc[3 * j + 1], pcjz = pc[3 * j + 2];
    float nix = nrm[3 * i], niy = nrm[3 * i + 1], niz = nrm[3 * i + 2];
    float njx = nrm[3 * j], njy = nrm[3 * j + 1], njz = nrm[3 * j + 2];
    float d = dist[(i << 10) + j];
    float inv = 1.0f / (d + 1e-7f);
    float xx0 = pcix - pcjx, xx1 = pciy - pcjy, xx2 = pciz - pcjz;
    float p[4];
    p[0] = (nix * xx0 + niy * xx1 + niz * xx2) * inv;
    p[1] = (njx * xx0 + njy * xx1 + njz * xx2) * inv;
    p[2] = nix * njx + niy * njy + niz * njz;
    p[3] = d;

    // ---- layer0: h = relu(A1[i]+B1[j]+ppf@w1p) ; res = A0[i]+B0[j]+ppf@w0p ----
    u64 acc[16], racc[16];
    {
        const u64* A1 = (const u64*)(g_A1 + (i << 5));
        const u64* B1 = (const u64*)(g_B1 + (j << 5));
        const u64* A0 = (const u64*)(g_A0 + (i << 5));
        const u64* B0 = (const u64*)(g_B0 + (j << 5));
#pragma unroll
        for (int n = 0; n < 16; n++) { acc[n] = add2(A1[n], B1[n]); racc[n] = add2(A0[n], B0[n]); }
#pragma unroll
        for (int k = 0; k < 4; k++) {
            u64 pw = pk2(p[k], p[k]);
            const u64* r1 = (const u64*)(s + O_W1P + (k << 5));
            const u64* r0 = (const u64*)(s + O_W0P + (k << 5));
#pragma unroll
            for (int n = 0; n < 16; n++) {
                acc[n]  = fma2(pw, r1[n], acc[n]);
                racc[n] = fma2(pw, r0[n], racc[n]);
            }
        }
    }
    float h[32];
#pragma unroll
    for (int n = 0; n < 16; n++) {
        float lo, hi; upk2(acc[n], lo, hi);
        h[2 * n] = fmaxf(lo, 0.f); h[2 * n + 1] = fmaxf(hi, 0.f);
    }

    // ---- x = h @ l0_fc2 + b + res ----
    float x[32];
    {
        u64 xa[16];
        const u64* bb = (const u64*)(s + O_L0B2);
#pragma unroll
        for (int n = 0; n < 16; n++) xa[n] = bb[n];
#pragma unroll
        for (int k = 0; k < 32; k++) {
            u64 hk = pk2(h[k], h[k]);
            const u64* w = (const u64*)(s + O_L0W2 + (k << 5));
#pragma unroll
            for (int n = 0; n < 16; n++) xa[n] = fma2(hk, w[n], xa[n]);
        }
#pragma unroll
        for (int n = 0; n < 16; n++) {
            xa[n] = add2(xa[n], racc[n]);
            float lo, hi; upk2(xa[n], lo, hi);
            x[2 * n] = lo; x[2 * n + 1] = hi;
        }
    }

    // ---- layer1: x = x + relu(x@W1+b1)@W2 + b2 ----
    {
        u64 ha[16];
        const u64* bb = (const u64*)(s + O_L1B1);
#pragma unroll
        for (int n = 0; n < 16; n++) ha[n] = bb[n];
#pragma unroll
        for (int k = 0; k < 32; k++) {
            u64 xk = pk2(x[k], x[k]);
            const u64* w = (const u64*)(s + O_L1W1 + (k << 5));
#pragma unroll
            for (int n = 0; n < 16; n++) ha[n] = fma2(xk, w[n], ha[n]);
        }
#pragma unroll
        for (int n = 0; n < 16; n++) {
            float lo, hi; upk2(ha[n], lo, hi);
            h[2 * n] = fmaxf(lo, 0.f); h[2 * n + 1] = fmaxf(hi, 0.f);
        }
        u64 xa[16];
        const u64* b2 = (const u64*)(s + O_L1B2);
#pragma unroll
        for (int n = 0; n < 16; n++) xa[n] = b2[n];
#pragma unroll
        for (int k = 0; k < 32; k++) {
            u64 hk = pk2(h[k], h[k]);
            const u64* w = (const u64*)(s + O_L1W2 + (k << 5));
#pragma unroll
            for (int n = 0; n < 16; n++) xa[n] = fma2(hk, w[n], xa[n]);
        }
#pragma unroll
        for (int n = 0; n < 16; n++) {
            xa[n] = add2(xa[n], pk2(x[2 * n], x[2 * n + 1]));
            float lo, hi; upk2(xa[n], lo, hi);
            x[2 * n] = lo; x[2 * n + 1] = hi;
        }
    }

    // ---- layer2: res = x@fc0+b0 (16); x3 = relu(x@fc1+b1)@fc2 + b2 + res ----
    float x3[16];
    {
        u64 r8[8], h8[8];
        const u64* b0p = (const u64*)(s + O_L2B0);
        const u64* b1p = (const u64*)(s + O_L2B1);
#pragma unroll
        for (int n = 0; n < 8; n++) { r8[n] = b0p[n]; h8[n] = b1p[n]; }
#pragma unroll
        for (int k = 0; k < 32; k++) {
            u64 xk = pk2(x[k], x[k]);
            const u64* w0r = (const u64*)(s + O_L2W0 + (k << 4));
            const u64* w1r = (const u64*)(s + O_L2W1 + (k << 4));
#pragma unroll
            for (int n = 0; n < 8; n++) {
                r8[n] = fma2(xk, w0r[n], r8[n]);
                h8[n] = fma2(xk, w1r[n], h8[n]);
            }
        }
        float h16[16];
#pragma unroll
        for (int n = 0; n < 8; n++) {
            float lo, hi; upk2(h8[n], lo, hi);
            h16[2 * n] = fmaxf(lo, 0.f); h16[2 * n + 1] = fmaxf(hi, 0.f);
        }
        u64 xa[8];
        const u64* b2p = (const u64*)(s + O_L2B2);
#pragma unroll
        for (int n = 0; n < 8; n++) xa[n] = b2p[n];
#pragma unroll
        for (int k = 0; k < 16; k++) {
            u64 hk = pk2(h16[k], h16[k]);
            const u64* w = (const u64*)(s + O_L2W2 + (k << 4));
#pragma unroll
            for (int n = 0; n < 8; n++) xa[n] = fma2(hk, w[n], xa[n]);
        }
#pragma unroll
        for (int n = 0; n < 8; n++) {
            xa[n] = add2(xa[n], r8[n]);
            float lo, hi; upk2(xa[n], lo, hi);
            x3[2 * n] = lo; x3[2 * n + 1] = hi;
        }
    }

    // ---- final: out = x3 @ final_w + final_b (16 -> 66) ----
    {
        u64 fa[33];
        const u64* fbp = (const u64*)(s + O_FB);
#pragma unroll
        for (int n = 0; n < 33; n++) fa[n] = fbp[n];
#pragma unroll
        for (int k = 0; k < 16; k++) {
            u64 xk = pk2(x3[k], x3[k]);
            const u64* w = (const u64*)(s + O_FW + k * 66);
#pragma unroll
            for (int n = 0; n < 33; n++) fa[n] = fma2(xk, w[n], fa[n]);
        }
        // stage to per-warp shared buffer, then coalesced write
        float* wb = s + O_OUT + warp * 2112 + lane * 66;
#pragma unroll
        for (int n = 0; n < 33; n++) {
            float lo, hi; upk2(fa[n], lo, hi);
            wb[2 * n] = lo; wb[2 * n + 1] = hi;
        }
        __syncwarp();
        const float* rb = s + O_OUT + warp * 2112;
        size_t base = (size_t)((i << 10) + ((blockIdx.x & 3) << 8) + (warp << 5)) * 66ull;
#pragma unroll 6
        for (int e = lane; e < 2112; e += 32) out[base + e] = rb[e];
    }
}

extern "C" void kernel_launch(void* const* d_in, const int* in_sizes, int n_in,
                              void* d_out, int out_size) {
    const float* pc   = (const float*)d_in[0];
    const float* nrm  = (const float*)d_in[1];
    const float* dist = (const float*)d_in[2];
    const float* feat = (const float*)d_in[3];
    const float* w0   = (const float*)d_in[4];   const float* b0   = (const float*)d_in[5];
    const float* w1   = (const float*)d_in[6];   const float* b1   = (const float*)d_in[7];
    const float* l0w2 = (const float*)d_in[8];   const float* l0b2 = (const float*)d_in[9];
    const float* l1w1 = (const float*)d_in[10];  const float* l1b1 = (const float*)d_in[11];
    const float* l1w2 = (const float*)d_in[12];  const float* l1b2 = (const float*)d_in[13];
    const float* l2w0 = (const float*)d_in[14];  const float* l2b0 = (const float*)d_in[15];
    const float* l2w1 = (const float*)d_in[16];  const float* l2b1 = (const float*)d_in[17];
    const float* l2w2 = (const float*)d_in[18];  const float* l2b2 = (const float*)d_in[19];
    const float* fw   = (const float*)d_in[20];  const float* fb   = (const float*)d_in[21];
    float* out = (float*)d_out;

    cudaFuncSetAttribute(ppf_main, cudaFuncAttributeMaxDynamicSharedMemorySize, SMEM_BYTES);

    ppf_pre<<<128, 256>>>(feat, w0, b0, w1, b1);
    ppf_main<<<4096, 256, SMEM_BYTES>>>(pc, nrm, dist, w0, w1,
                                        l0w2, l0b2, l1w1, l1b1, l1w2, l1b2,
                                        l2w0, l2b0, l2w1, l2b1, l2w2, l2b2,
                                        fw, fb, out);
}

// round 2
// speedup vs baseline: 1.0124x; 1.0124x over previous
#include <cuda_runtime.h>
#include <cstdint>

typedef unsigned long long u64;

// ---------- f32x2 packed math (sm_103a) ----------
__device__ __forceinline__ u64 pk2(float lo, float hi) {
    u64 r;
    asm("mov.b64 %0, {%1, %2};" : "=l"(r) : "r"(__float_as_uint(lo)), "r"(__float_as_uint(hi)));
    return r;
}
__device__ __forceinline__ void upk2(u64 v, float& lo, float& hi) {
    unsigned a, b;
    asm("mov.b64 {%0, %1}, %2;" : "=r"(a), "=r"(b) : "l"(v));
    lo = __uint_as_float(a); hi = __uint_as_float(b);
}
__device__ __forceinline__ u64 fma2(u64 a, u64 b, u64 c) {
    u64 d;
    asm("fma.rn.f32x2 %0, %1, %2, %3;" : "=l"(d) : "l"(a), "l"(b), "l"(c));
    return d;
}
__device__ __forceinline__ u64 add2(u64 a, u64 b) {
    u64 d;
    asm("add.rn.f32x2 %0, %1, %2;" : "=l"(d) : "l"(a), "l"(b));
    return d;
}

// ---------- per-point precomputed first-layer projections ----------
__device__ float g_A0[1024 * 32];
__device__ float g_B0[1024 * 32];
__device__ float g_A1[1024 * 32];
__device__ float g_B1[1024 * 32];

__global__ void ppf_pre(const float* __restrict__ feat,
                        const float* __restrict__ w0, const float* __restrict__ b0,
                        const float* __restrict__ w1, const float* __restrict__ b1) {
    int t = blockIdx.x * blockDim.x + threadIdx.x;   // 32768 threads
    int i = t >> 5, c = t & 31;
    const float* f = feat + i * 40;
    float a0 = b0[c], bo0 = 0.f, a1 = b1[c], bo1 = 0.f;
#pragma unroll 8
    for (int k = 0; k < 40; k++) {
        float fv = f[k];
        a0  = fmaf(fv, w0[k * 32 + c],        a0);
        bo0 = fmaf(fv, w0[(k + 40) * 32 + c], bo0);
        a1  = fmaf(fv, w1[k * 32 + c],        a1);
        bo1 = fmaf(fv, w1[(k + 40) * 32 + c], bo1);
    }
    g_A0[i * 32 + c] = a0;
    g_B0[i * 32 + c] = bo0;
    g_A1[i * 32 + c] = a1;
    g_B1[i * 32 + c] = bo1;
}

// ---------- shared memory layout (units: floats, all 16-float aligned) ----------
#define O_W0P   0          // [4][32]
#define O_W1P   128        // [4][32]
#define O_L0W2  256        // [32][32]
#define O_L0B2  1280       // [32]
#define O_L1W1  1312       // [32][32]
#define O_L1B1  2336       // [32]
#define O_L1W2  2368       // [32][32]
#define O_L1B2  3392       // [32]
#define O_L2W0  3424       // [32][16]
#define O_L2B0  3936       // [16]
#define O_L2W1  3952       // [32][16]
#define O_L2B1  4464       // [16]
#define O_L2W2  4480       // [16][16]
#define O_L2B2  4736       // [16]
#define O_FW    4752       // [16][66]
#define O_FB    5808       // [66]
#define O_OUT   5888       // 8 warps * 64 rows * 66
#define SMEM_FLOATS (5888 + 8 * 64 * 66)
#define SMEM_BYTES  (SMEM_FLOATS * 4)

// ---- 32->32 GEMM, 2 pairs, float4 weight loads, bias init ----
__device__ __forceinline__ void gemm32x32(const float* __restrict__ s, int woff, int boff,
                                          const float x[2][32], u64 acc[2][16]) {
    const u64* bb = (const u64*)(s + boff);
#pragma unroll
    for (int n = 0; n < 16; n++) { u64 b = bb[n]; acc[0][n] = b; acc[1][n] = b; }
#pragma unroll
    for (int k = 0; k < 32; k++) {
        u64 xs0 = pk2(x[0][k], x[0][k]);
        u64 xs1 = pk2(x[1][k], x[1][k]);
        const float4* w = (const float4*)(s + woff + (k << 5));
#pragma unroll
        for (int n4 = 0; n4 < 8; n4++) {
            float4 wv = w[n4];
            u64 wlo = pk2(wv.x, wv.y), whi = pk2(wv.z, wv.w);
            acc[0][2 * n4]     = fma2(xs0, wlo, acc[0][2 * n4]);
            acc[1][2 * n4]     = fma2(xs1, wlo, acc[1][2 * n4]);
            acc[0][2 * n4 + 1] = fma2(xs0, whi, acc[0][2 * n4 + 1]);
            acc[1][2 * n4 + 1] = fma2(xs1, whi, acc[1][2 * n4 + 1]);
        }
    }
}

// ---- 32->16 GEMM, 2 pairs ----
__device__ __forceinline__ void gemm32x16(const float* __restrict__ s, int woff, int boff,
                                          const float x[2][32], u64 acc[2][8]) {
    const u64* bb = (const u64*)(s + boff);
#pragma unroll
    for (int n = 0; n < 8; n++) { u64 b = bb[n]; acc[0][n] = b; acc[1][n] = b; }
#pragma unroll
    for (int k = 0; k < 32; k++) {
        u64 xs0 = pk2(x[0][k], x[0][k]);
        u64 xs1 = pk2(x[1][k], x[1][k]);
        const float4* w = (const float4*)(s + woff + (k << 4));
#pragma unroll
        for (int n4 = 0; n4 < 4; n4++) {
            float4 wv = w[n4];
            u64 wlo = pk2(wv.x, wv.y), whi = pk2(wv.z, wv.w);
            acc[0][2 * n4]     = fma2(xs0, wlo, acc[0][2 * n4]);
            acc[1][2 * n4]     = fma2(xs1, wlo, acc[1][2 * n4]);
            acc[0][2 * n4 + 1] = fma2(xs0, whi, acc[0][2 * n4 + 1]);
            acc[1][2 * n4 + 1] = fma2(xs1, whi, acc[1][2 * n4 + 1]);
        }
    }
}

// ---- 16->16 GEMM, 2 pairs ----
__device__ __forceinline__ void gemm16x16(const float* __restrict__ s, int woff, int boff,
                                          const float x[2][16], u64 acc[2][8]) {
    const u64* bb = (const u64*)(s + boff);
#pragma unroll
    for (int n = 0; n < 8; n++) { u64 b = bb[n]; acc[0][n] = b; acc[1][n] = b; }
#pragma unroll
    for (int k = 0; k < 16; k++) {
        u64 xs0 = pk2(x[0][k], x[0][k]);
        u64 xs1 = pk2(x[1][k], x[1][k]);
        const float4* w = (const float4*)(s + woff + (k << 4));
#pragma unroll
        for (int n4 = 0; n4 < 4; n4++) {
            float4 wv = w[n4];
            u64 wlo = pk2(wv.x, wv.y), whi = pk2(wv.z, wv.w);
            acc[0][2 * n4]     = fma2(xs0, wlo, acc[0][2 * n4]);
            acc[1][2 * n4]     = fma2(xs1, wlo, acc[1][2 * n4]);
            acc[0][2 * n4 + 1] = fma2(xs0, whi, acc[0][2 * n4 + 1]);
            acc[1][2 * n4 + 1] = fma2(xs1, whi, acc[1][2 * n4 + 1]);
        }
    }
}

__global__ __launch_bounds__(256)
void ppf_main(const float* __restrict__ pc, const float* __restrict__ nrm,
              const float* __restrict__ dist,
              const float* __restrict__ fc0w, const float* __restrict__ fc1w,
              const float* __restrict__ l0w2, const float* __restrict__ l0b2,
              const float* __restrict__ l1w1, const float* __restrict__ l1b1,
              const float* __restrict__ l1w2, const float* __restrict__ l1b2,
              const float* __restrict__ l2w0, const float* __restrict__ l2b0,
              const float* __restrict__ l2w1, const float* __restrict__ l2b1,
              const float* __restrict__ l2w2, const float* __restrict__ l2b2,
              const float* __restrict__ fw, const float* __restrict__ fb,
              float* __restrict__ out) {
    extern __shared__ float s[];
    const int tid = threadIdx.x;
    const int lane = tid & 31;
    const int warp = tid >> 5;

    // cooperative weight staging
    {
        for (int t = tid; t < 128; t += 256)  s[O_W0P + t] = fc0w[80 * 32 + t];
        for (int t = tid; t < 128; t += 256)  s[O_W1P + t] = fc1w[80 * 32 + t];
        for (int t = tid; t < 1024; t += 256) s[O_L0W2 + t] = l0w2[t];
        for (int t = tid; t < 32; t += 256)   s[O_L0B2 + t] = l0b2[t];
        for (int t = tid; t < 1024; t += 256) s[O_L1W1 + t] = l1w1[t];
        for (int t = tid; t < 32; t += 256)   s[O_L1B1 + t] = l1b1[t];
        for (int t = tid; t < 1024; t += 256) s[O_L1W2 + t] = l1w2[t];
        for (int t = tid; t < 32; t += 256)   s[O_L1B2 + t] = l1b2[t];
        for (int t = tid; t < 512; t += 256)  s[O_L2W0 + t] = l2w0[t];
        for (int t = tid; t < 16; t += 256)   s[O_L2B0 + t] = l2b0[t];
        for (int t = tid; t < 512; t += 256)  s[O_L2W1 + t] = l2w1[t];
        for (int t = tid; t < 16; t += 256)   s[O_L2B1 + t] = l2b1[t];
        for (int t = tid; t < 256; t += 256)  s[O_L2W2 + t] = l2w2[t];
        for (int t = tid; t < 16; t += 256)   s[O_L2B2 + t] = l2b2[t];
        for (int t = tid; t < 1056; t += 256) s[O_FW + t] = fw[t];
        for (int t = tid; t < 66; t += 256)   s[O_FB + t] = fb[t];
    }
    __syncthreads();

    // 2 pairs per thread: (i, jb+lane) and (i, jb+lane+32); each warp owns 64 j-rows
    const int i = blockIdx.x >> 1;
    const int jb = ((blockIdx.x & 1) << 9) + (warp << 6);
    const int j0 = jb + lane;
    const int j1 = j0 + 32;

    // ---- PPF features for both pairs ----
    float pcix = pc[3 * i], pciy = pc[3 * i + 1], pciz = pc[3 * i + 2];
    float nix = nrm[3 * i], niy = nrm[3 * i + 1], niz = nrm[3 * i + 2];
    float p[2][4];
#pragma unroll
    for (int pr = 0; pr < 2; pr++) {
        int j = pr ? j1 : j0;
        float pcjx = pc[3 * j], pcjy = pc[3 * j + 1], pcjz = pc[3 * j + 2];
        float njx = nrm[3 * j], njy = nrm[3 * j + 1], njz = nrm[3 * j + 2];
        float d = dist[(i << 10) + j];
        float inv = 1.0f / (d + 1e-7f);
        float xx0 = pcix - pcjx, xx1 = pciy - pcjy, xx2 = pciz - pcjz;
        p[pr][0] = (nix * xx0 + niy * xx1 + niz * xx2) * inv;
        p[pr][1] = (njx * xx0 + njy * xx1 + njz * xx2) * inv;
        p[pr][2] = nix * njx + niy * njy + niz * njz;
        p[pr][3] = d;
    }

    // ---- layer0 pre-activation + residual ----
    u64 acc[2][16], racc[2][16];
    {
        const u64* A1 = (const u64*)(g_A1 + (i << 5));
        const u64* A0 = (const u64*)(g_A0 + (i << 5));
        const u64* B1a = (const u64*)(g_B1 + (j0 << 5));
        const u64* B1b = (const u64*)(g_B1 + (j1 << 5));
        const u64* B0a = (const u64*)(g_B0 + (j0 << 5));
        const u64* B0b = (const u64*)(g_B0 + (j1 << 5));
#pragma unroll
        for (int n = 0; n < 16; n++) {
            u64 a1 = A1[n], a0 = A0[n];
            acc[0][n]  = add2(a1, B1a[n]);
            acc[1][n]  = add2(a1, B1b[n]);
            racc[0][n] = add2(a0, B0a[n]);
            racc[1][n] = add2(a0, B0b[n]);
        }
#pragma unroll
        for (int k = 0; k < 4; k++) {
            u64 pw0 = pk2(p[0][k], p[0][k]);
            u64 pw1 = pk2(p[1][k], p[1][k]);
            const float4* r1 = (const float4*)(s + O_W1P + (k << 5));
            const float4* r0 = (const float4*)(s + O_W0P + (k << 5));
#pragma unroll
            for (int n4 = 0; n4 < 8; n4++) {
                float4 wv1 = r1[n4], wv0 = r0[n4];
                u64 w1lo = pk2(wv1.x, wv1.y), w1hi = pk2(wv1.z, wv1.w);
                u64 w0lo = pk2(wv0.x, wv0.y), w0hi = pk2(wv0.z, wv0.w);
                acc[0][2 * n4]      = fma2(pw0, w1lo, acc[0][2 * n4]);
                acc[1][2 * n4]      = fma2(pw1, w1lo, acc[1][2 * n4]);
                acc[0][2 * n4 + 1]  = fma2(pw0, w1hi, acc[0][2 * n4 + 1]);
                acc[1][2 * n4 + 1]  = fma2(pw1, w1hi, acc[1][2 * n4 + 1]);
                racc[0][2 * n4]     = fma2(pw0, w0lo, racc[0][2 * n4]);
                racc[1][2 * n4]     = fma2(pw1, w0lo, racc[1][2 * n4]);
                racc[0][2 * n4 + 1] = fma2(pw0, w0hi, racc[0][2 * n4 + 1]);
                racc[1][2 * n4 + 1] = fma2(pw1, w0hi, racc[1][2 * n4 + 1]);
            }
        }
    }

    float h[2][32];
#pragma unroll
    for (int pr = 0; pr < 2; pr++)
#pragma unroll
        for (int n = 0; n < 16; n++) {
            float lo, hi; upk2(acc[pr][n], lo, hi);
            h[pr][2 * n] = fmaxf(lo, 0.f); h[pr][2 * n + 1] = fmaxf(hi, 0.f);
        }

    // ---- x = h @ l0_fc2 + b + res ----
    float x[2][32];
    {
        u64 xa[2][16];
        gemm32x32(s, O_L0W2, O_L0B2, h, xa);
#pragma unroll
        for (int pr = 0; pr < 2; pr++)
#pragma unroll
            for (int n = 0; n < 16; n++) {
                u64 v = add2(xa[pr][n], racc[pr][n]);
                float lo, hi; upk2(v, lo, hi);
                x[pr][2 * n] = lo; x[pr][2 * n + 1] = hi;
            }
    }

    // ---- layer1 ----
    {
        u64 ha[2][16];
        gemm32x32(s, O_L1W1, O_L1B1, x, ha);
#pragma unroll
        for (int pr = 0; pr < 2; pr++)
#pragma unroll
            for (int n = 0; n < 16; n++) {
                float lo, hi; upk2(ha[pr][n], lo, hi);
                h[pr][2 * n] = fmaxf(lo, 0.f); h[pr][2 * n + 1] = fmaxf(hi, 0.f);
            }
        u64 xa[2][16];
        gemm32x32(s, O_L1W2, O_L1B2, h, xa);
#pragma unroll
        for (int pr = 0; pr < 2; pr++)
#pragma unroll
            for (int n = 0; n < 16; n++) {
                u64 v = add2(xa[pr][n], pk2(x[pr][2 * n], x[pr][2 * n + 1]));
                float lo, hi; upk2(v, lo, hi);
                x[pr][2 * n] = lo; x[pr][2 * n + 1] = hi;
            }
    }

    // ---- layer2 ----
    float x3[2][16];
    {
        u64 r8[2][8], h8[2][8];
        gemm32x16(s, O_L2W0, O_L2B0, x, r8);
        gemm32x16(s, O_L2W1, O_L2B1, x, h8);
        float h16[2][16];
#pragma unroll
        for (int pr = 0; pr < 2; pr++)
#pragma unroll
            for (int n = 0; n < 8; n++) {
                float lo, hi; upk2(h8[pr][n], lo, hi);
                h16[pr][2 * n] = fmaxf(lo, 0.f); h16[pr][2 * n + 1] = fmaxf(hi, 0.f);
            }
        u64 xa[2][8];
        gemm16x16(s, O_L2W2, O_L2B2, h16, xa);
#pragma unroll
        for (int pr = 0; pr < 2; pr++)
#pragma unroll
            for (int n = 0; n < 8; n++) {
                u64 v = add2(xa[pr][n], r8[pr][n]);
                float lo, hi; upk2(v, lo, hi);
                x3[pr][2 * n] = lo; x3[pr][2 * n + 1] = hi;
            }
    }

    // ---- final 16 -> 66, chunked (3 chunks of 22 floats = 11 u64) ----
    // stage both pairs into per-warp shared buffer (64 rows x 66), then one
    // fully-contiguous float4 copy-out per warp.
    {
        float* wbase = s + O_OUT + warp * (64 * 66);
        u64* wb0 = (u64*)(wbase + lane * 66);
        u64* wb1 = (u64*)(wbase + (lane + 32) * 66);
#pragma unroll
        for (int c = 0; c < 3; c++) {
            u64 fa[2][11];
            const u64* fbp = (const u64*)(s + O_FB) + c * 11;
#pragma unroll
            for (int n = 0; n < 11; n++) { u64 b = fbp[n]; fa[0][n] = b; fa[1][n] = b; }
#pragma unroll
            for (int k = 0; k < 16; k++) {
                u64 xs0 = pk2(x3[0][k], x3[0][k]);
                u64 xs1 = pk2(x3[1][k], x3[1][k]);
                const u64* w = (const u64*)(s + O_FW + k * 66) + c * 11;
#pragma unroll
                for (int n = 0; n < 11; n++) {
                    u64 wv = w[n];
                    fa[0][n] = fma2(xs0, wv, fa[0][n]);
                    fa[1][n] = fma2(xs1, wv, fa[1][n]);
                }
            }
#pragma unroll
            for (int n = 0; n < 11; n++) {
                wb0[c * 11 + n] = fa[0][n];
                wb1[c * 11 + n] = fa[1][n];
            }
        }
        __syncwarp();
        // copy 64 rows x 66 floats = 4224 floats = 1056 float4, contiguous in gmem
        const float4* rb = (const float4*)wbase;
        float4* ob = (float4*)(out + (size_t)((i << 10) + jb) * 66ull);
#pragma unroll 4
        for (int e = lane; e < 1056; e += 32) ob[e] = rb[e];
    }
}

extern "C" void kernel_launch(void* const* d_in, const int* in_sizes, int n_in,
                              void* d_out, int out_size) {
    const float* pc   = (const float*)d_in[0];
    const float* nrm  = (const float*)d_in[1];
    const float* dist = (const float*)d_in[2];
    const float* feat = (const float*)d_in[3];
    const float* w0   = (const float*)d_in[4];   const float* b0   = (const float*)d_in[5];
    const float* w1   = (const float*)d_in[6];   const float* b1   = (const float*)d_in[7];
    const float* l0w2 = (const float*)d_in[8];   const float* l0b2 = (const float*)d_in[9];
    const float* l1w1 = (const float*)d_in[10];  const float* l1b1 = (const float*)d_in[11];
    const float* l1w2 = (const float*)d_in[12];  const float* l1b2 = (const float*)d_in[13];
    const float* l2w0 = (const float*)d_in[14];  const float* l2b0 = (const float*)d_in[15];
    const float* l2w1 = (const float*)d_in[16];  const float* l2b1 = (const float*)d_in[17];
    const float* l2w2 = (const float*)d_in[18];  const float* l2b2 = (const float*)d_in[19];
    const float* fw   = (const float*)d_in[20];  const float* fb   = (const float*)d_in[21];
    float* out = (float*)d_out;

    cudaFuncSetAttribute(ppf_main, cudaFuncAttributeMaxDynamicSharedMemorySize, SMEM_BYTES);

    ppf_pre<<<128, 256>>>(feat, w0, b0, w1, b1);
    ppf_main<<<2048, 256, SMEM_BYTES>>>(pc, nrm, dist, w0, w1,
                                        l0w2, l0b2, l1w1, l1b1, l1w2, l1b2,
                                        l2w0, l2b0, l2w1, l2b1, l2w2, l2b2,
                                        fw, fb, out);
}